// round 3
// baseline (speedup 1.0000x reference)
#include <cuda_runtime.h>
#include <cuda_bf16.h>
#include <math.h>

#define HH 28
#define WW 28
#define LW 12
#define KL 25
#define NPIX (HH*WW)

__global__ __launch_bounds__(NPIX, 1)
void FMNISTCanny_kernel(const float* __restrict__ x,
                        const float* __restrict__ mask,
                        const float* __restrict__ g,
                        float* __restrict__ out) {
    __shared__ float xs_[HH][WW];   // x
    __shared__ float ms_[HH][WW];   // mask
    __shared__ float t1[HH][WW];    // temp (x vertical pass) -> xs final
    __shared__ float t2[HH][WW];    // temp (mask vertical pass)
    __shared__ float magS[HH][WW];
    __shared__ float gk[KL];
    __shared__ unsigned char hiS[HH][WW], loS[HH][WW];
    __shared__ unsigned finalm[HH];

    const int c = threadIdx.x;
    const int r = threadIdx.y;
    const int idx = r * WW + c;

    if (idx < KL) gk[idx] = g[idx];
    xs_[r][c] = x[idx];
    ms_[r][c] = mask[idx];
    __syncthreads();

    // ---- Gaussian: vertical (H) pass, zero padding ----
    float ax = 0.f, am = 0.f;
    #pragma unroll
    for (int d = -LW; d <= LW; ++d) {
        int rr = r + d;
        if (rr >= 0 && rr < HH) {
            float w = gk[d + LW];
            ax += w * xs_[rr][c];
            am += w * ms_[rr][c];
        }
    }
    t1[r][c] = ax;
    t2[r][c] = am;
    __syncthreads();

    // ---- Gaussian: horizontal (W) pass, zero padding; then normalize ----
    ax = 0.f; am = 0.f;
    #pragma unroll
    for (int d = -LW; d <= LW; ++d) {
        int cc = c + d;
        if (cc >= 0 && cc < WW) {
            float w = gk[d + LW];
            ax += w * t1[r][cc];
            am += w * t2[r][cc];
        }
    }
    float xsv = ax / (am + 1e-12f);
    __syncthreads();          // all reads of t1/t2 done
    t1[r][c] = xsv;           // t1 now holds xs
    __syncthreads();

    // ---- Sobel with replicate padding ----
    const int rm = r > 0 ? r - 1 : 0;
    const int rp = r < HH - 1 ? r + 1 : HH - 1;
    const int cm = c > 0 ? c - 1 : 0;
    const int cp = c < WW - 1 ? c + 1 : WW - 1;

    // isob = smooth_W(deriv_H(xs))
    float isob = (t1[rp][cm] - t1[rm][cm])
               + 2.f * (t1[rp][c] - t1[rm][c])
               + (t1[rp][cp] - t1[rm][cp]);
    // jsob = smooth_H(deriv_W(xs))
    float jsob = (t1[rm][cp] - t1[rm][cm])
               + 2.f * (t1[r][cp] - t1[r][cm])
               + (t1[rp][cp] - t1[rp][cm]);

    float mag2 = isob * isob + jsob * jsob;
    float m = sqrtf(mag2 + 1e-9f);
    magS[r][c] = m;

    // ---- 3x3 erosion of mask (zero border) ----
    bool er2 = (r > 0) && (r < HH - 1) && (c > 0) && (c < WW - 1);
    if (er2) {
        #pragma unroll
        for (int dr = -1; dr <= 1; ++dr)
            #pragma unroll
            for (int dc = -1; dc <= 1; ++dc)
                er2 = er2 && (ms_[r + dr][c + dc] != 0.f);
    }
    const bool er = er2 && (mag2 > 0.f);
    __syncthreads();  // magS ready for neighbor reads

    const float ai = fabsf(isob);
    const float aj = fabsf(jsob);
    const bool same = ((isob >= 0.f) && (jsob >= 0.f)) || ((isob <= 0.f) && (jsob <= 0.f));
    const bool opp  = ((isob <= 0.f) && (jsob >= 0.f)) || ((isob >= 0.f) && (jsob <= 0.f));

    // nb(dr,dc): mag at (r+dr, c+dc) with zero padding
    #define NB(dr, dc) ((r+(dr) >= 0 && r+(dr) < HH && c+(dc) >= 0 && c+(dc) < WW) \
                         ? magS[r+(dr)][c+(dc)] : 0.f)
    const float GAMMA = 0.005f;

    // sector 0 (0-45): c1p=nb(1,0) c2p=nb(1,1) c1m=nb(-1,0) c2m=nb(-1,-1)
    bool pts0 = er && same && (ai >= aj);
    float w0  = aj / (ai + 1e-9f);
    float ip0 = NB(1, 1) * w0 + NB(1, 0) * (1.f - w0);
    float im0 = NB(-1, -1) * w0 + NB(-1, 0) * (1.f - w0);
    float s0v = pts0 ? fmaxf(fmaxf(0.f, GAMMA - m + ip0), fmaxf(0.f, GAMMA - m + im0)) : 0.f;
    bool  l0  = (ip0 <= m) && (im0 <= m);

    // sector 1 (45-90): c1p=nb(0,1) c2p=nb(1,1) c1m=nb(0,-1) c2m=nb(-1,-1)
    bool pts1 = er && same && (ai <= aj);
    float w1  = ai / (pts1 ? aj : 1.f);
    float ip1 = NB(1, 1) * w1 + NB(0, 1) * (1.f - w1);
    float im1 = NB(-1, -1) * w1 + NB(0, -1) * (1.f - w1);
    float s1v = pts1 ? fmaxf(fmaxf(0.f, GAMMA - m + ip1), fmaxf(0.f, GAMMA - m + im1)) : 0.f;
    bool  l1  = (ip1 <= m) && (im1 <= m);

    // sector 2 (90-135, faithful quirk: s2 reuses ip): c1p=nb(0,1) c2p=nb(-1,1) c1m=nb(0,-1) c2m=nb(1,-1)
    bool pts2 = er && opp && (ai <= aj);
    float w2  = ai / (pts2 ? aj : 1.f);
    float ip2 = NB(-1, 1) * w2 + NB(0, 1) * (1.f - w2);
    float im2 = NB(1, -1) * w2 + NB(0, -1) * (1.f - w2);
    float s2v = pts2 ? fmaxf(0.f, GAMMA - m + ip2) : 0.f;   // max(s1,s2) with s2==s1
    bool  l2  = (ip2 <= m) && (im2 <= m);

    // sector 3 (135-180): c1p=nb(-1,0) c2p=nb(-1,1) c1m=nb(1,0) c2m=nb(1,-1)
    bool pts3 = er && opp && (ai >= aj);
    float w3  = aj / (pts3 ? ai : 1.f);
    float ip3 = NB(-1, 1) * w3 + NB(-1, 0) * (1.f - w3);
    float im3 = NB(1, -1) * w3 + NB(1, 0) * (1.f - w3);
    float s3v = pts3 ? fmaxf(fmaxf(0.f, GAMMA - m + ip3), fmaxf(0.f, GAMMA - m + im3)) : 0.f;
    bool  l3  = (ip3 <= m) && (im3 <= m);
    #undef NB

    // sequential overwrite (order 0,1,2,3)
    bool lm = false;
    if (pts0) lm = l0;
    if (pts1) lm = l1;
    if (pts2) lm = l2;
    if (pts3) lm = l3;

    // ---- hysteresis thresholds ----
    hiS[r][c] = (lm && (m >= 0.2f)) ? 1 : 0;
    loS[r][c] = (lm && (m >= 0.1f)) ? 1 : 0;
    __syncthreads();

    // ---- hysteresis: pack rows into 28-bit masks, dilate in one warp ----
    if (idx < HH) {   // lanes 0..27 of warp 0
        unsigned lo = 0u, cur = 0u;
        #pragma unroll
        for (int j = 0; j < WW; ++j) {
            lo  |= ((unsigned)loS[idx][j]) << j;
            cur |= ((unsigned)hiS[idx][j]) << j;
        }
        const unsigned MSK = 0x0FFFFFFFu;
        #pragma unroll 4
        for (int it = 0; it < 2 * HH; ++it) {
            unsigned sp = cur | (cur << 1) | (cur >> 1);
            unsigned up = __shfl_up_sync(MSK, sp, 1);
            unsigned dn = __shfl_down_sync(MSK, sp, 1);
            if (idx == 0)      up = 0u;
            if (idx == HH - 1) dn = 0u;
            cur = (sp | up | dn) & lo;
        }
        finalm[idx] = cur;
    }
    __syncthreads();

    const float fm = ((finalm[r] >> c) & 1u) ? 1.f : 0.f;

    // ---- outputs: (s0, s1, s2, s3, lm, test, mag_out) flattened ----
    out[0 * NPIX + idx] = s0v;
    out[1 * NPIX + idx] = s1v;
    out[2 * NPIX + idx] = s2v;
    out[3 * NPIX + idx] = s3v;
    out[4 * NPIX + idx] = lm ? 1.f : 0.f;
    out[5 * NPIX + idx] = 1.f;
    out[6 * NPIX + idx] = fm;   // mag_out == mask_final exactly (mag - mag == 0)
}

extern "C" void kernel_launch(void* const* d_in, const int* in_sizes, int n_in,
                              void* d_out, int out_size) {
    const float* x    = (const float*)d_in[0];
    const float* mask = (const float*)d_in[1];
    const float* g    = (const float*)d_in[2];
    float* out = (float*)d_out;
    dim3 blk(WW, HH);
    FMNISTCanny_kernel<<<1, blk>>>(x, mask, g, out);
}

// round 4
// speedup vs baseline: 1.2353x; 1.2353x over previous
#include <cuda_runtime.h>
#include <cuda_bf16.h>
#include <math.h>

#define HH 28
#define WW 28
#define LW 12
#define KL 25
#define NPIX (HH*WW)

__global__ __launch_bounds__(NPIX, 1)
void FMNISTCanny_kernel(const float* __restrict__ x,
                        const float* __restrict__ mask,
                        const float* __restrict__ g,
                        float* __restrict__ out) {
    // interleaved {x, mask}, zero-padded by LW rows on each side: rows 0..51
    __shared__ float2 xm[HH + 2 * LW][WW];
    // interleaved vertical-pass result, zero-padded by LW cols each side: cols 0..51
    __shared__ float2 t12[HH][WW + 2 * LW];
    __shared__ float  xsS[HH][WW];          // normalized smoothed image
    __shared__ float  magP[HH + 2][WW + 2]; // mag with zero border
    __shared__ float  gk[KL];
    __shared__ unsigned hiw[HH], low[HH], finalw[HH];

    const int c = threadIdx.x;
    const int r = threadIdx.y;
    const int idx = r * WW + c;

    // ---- loads + pad init ----
    if (idx < KL) gk[idx] = g[idx];
    if (r < LW) {                       // zero row pads of xm (top+bottom)
        xm[r][c]           = make_float2(0.f, 0.f);
        xm[r + HH + LW][c] = make_float2(0.f, 0.f);
    }
    if (c < LW) {                       // zero col pads of t12 (left+right)
        t12[r][c]           = make_float2(0.f, 0.f);
        t12[r][c + WW + LW] = make_float2(0.f, 0.f);
    }
    // zero border of magP (116 cells)
    if (idx < 30)            magP[0][idx]            = 0.f;
    else if (idx < 60)       magP[HH + 1][idx - 30]  = 0.f;
    else if (idx < 88)       magP[idx - 60 + 1][0]      = 0.f;
    else if (idx < 116)      magP[idx - 88 + 1][WW + 1] = 0.f;
    if (idx < HH) { hiw[idx] = 0u; low[idx] = 0u; }
    xm[r + LW][c] = make_float2(x[idx], mask[idx]);
    __syncthreads();

    // ---- Gaussian: vertical (H) pass (zero taps included, matches reference) ----
    float ax = 0.f, am = 0.f;
    #pragma unroll
    for (int d = 0; d < KL; ++d) {
        float w = gk[d];
        float2 v = xm[r + d][c];        // logical row r + d - LW, pad offset +LW
        ax += w * v.x;
        am += w * v.y;
    }
    t12[r][c + LW] = make_float2(ax, am);
    __syncthreads();

    // ---- Gaussian: horizontal (W) pass; then normalize ----
    ax = 0.f; am = 0.f;
    #pragma unroll
    for (int d = 0; d < KL; ++d) {
        float w = gk[d];
        float2 v = t12[r][c + d];       // logical col c + d - LW, pad offset +LW
        ax += w * v.x;
        am += w * v.y;
    }
    xsS[r][c] = ax / (am + 1e-12f);
    __syncthreads();

    // ---- Sobel with replicate padding ----
    const int rm = r > 0 ? r - 1 : 0;
    const int rp = r < HH - 1 ? r + 1 : HH - 1;
    const int cm = c > 0 ? c - 1 : 0;
    const int cp = c < WW - 1 ? c + 1 : WW - 1;

    float isob = (xsS[rp][cm] - xsS[rm][cm])
               + 2.f * (xsS[rp][c] - xsS[rm][c])
               + (xsS[rp][cp] - xsS[rm][cp]);
    float jsob = (xsS[rm][cp] - xsS[rm][cm])
               + 2.f * (xsS[r][cp] - xsS[r][cm])
               + (xsS[rp][cp] - xsS[rp][cm]);

    float mag2 = isob * isob + jsob * jsob;
    float m = sqrtf(mag2 + 1e-9f);
    magP[r + 1][c + 1] = m;

    // ---- 3x3 erosion of mask (zero border) ----
    bool er2 = (r > 0) && (r < HH - 1) && (c > 0) && (c < WW - 1);
    if (er2) {
        #pragma unroll
        for (int dr = -1; dr <= 1; ++dr)
            #pragma unroll
            for (int dc = -1; dc <= 1; ++dc)
                er2 = er2 && (xm[r + LW + dr][c + dc].y != 0.f);
    }
    const bool er = er2 && (mag2 > 0.f);
    __syncthreads();  // magP ready

    const float ai = fabsf(isob);
    const float aj = fabsf(jsob);
    const bool same = ((isob >= 0.f) && (jsob >= 0.f)) || ((isob <= 0.f) && (jsob <= 0.f));
    const bool opp  = ((isob <= 0.f) && (jsob >= 0.f)) || ((isob >= 0.f) && (jsob <= 0.f));

    #define NB(dr, dc) magP[r + 1 + (dr)][c + 1 + (dc)]
    const float GAMMA = 0.005f;

    // sector 0 (0-45)
    bool pts0 = er && same && (ai >= aj);
    float w0  = aj / (ai + 1e-9f);
    float ip0 = NB(1, 1) * w0 + NB(1, 0) * (1.f - w0);
    float im0 = NB(-1, -1) * w0 + NB(-1, 0) * (1.f - w0);
    float s0v = pts0 ? fmaxf(fmaxf(0.f, GAMMA - m + ip0), fmaxf(0.f, GAMMA - m + im0)) : 0.f;
    bool  l0  = (ip0 <= m) && (im0 <= m);

    // sector 1 (45-90)
    bool pts1 = er && same && (ai <= aj);
    float w1  = ai / (pts1 ? aj : 1.f);
    float ip1 = NB(1, 1) * w1 + NB(0, 1) * (1.f - w1);
    float im1 = NB(-1, -1) * w1 + NB(0, -1) * (1.f - w1);
    float s1v = pts1 ? fmaxf(fmaxf(0.f, GAMMA - m + ip1), fmaxf(0.f, GAMMA - m + im1)) : 0.f;
    bool  l1  = (ip1 <= m) && (im1 <= m);

    // sector 2 (90-135, faithful quirk: s2 reuses ip)
    bool pts2 = er && opp && (ai <= aj);
    float w2  = ai / (pts2 ? aj : 1.f);
    float ip2 = NB(-1, 1) * w2 + NB(0, 1) * (1.f - w2);
    float im2 = NB(1, -1) * w2 + NB(0, -1) * (1.f - w2);
    float s2v = pts2 ? fmaxf(0.f, GAMMA - m + ip2) : 0.f;
    bool  l2  = (ip2 <= m) && (im2 <= m);

    // sector 3 (135-180)
    bool pts3 = er && opp && (ai >= aj);
    float w3  = aj / (pts3 ? ai : 1.f);
    float ip3 = NB(-1, 1) * w3 + NB(-1, 0) * (1.f - w3);
    float im3 = NB(1, -1) * w3 + NB(1, 0) * (1.f - w3);
    float s3v = pts3 ? fmaxf(fmaxf(0.f, GAMMA - m + ip3), fmaxf(0.f, GAMMA - m + im3)) : 0.f;
    bool  l3  = (ip3 <= m) && (im3 <= m);
    #undef NB

    // sequential overwrite (order 0,1,2,3)
    bool lm = false;
    if (pts0) lm = l0;
    if (pts1) lm = l1;
    if (pts2) lm = l2;
    if (pts3) lm = l3;

    // ---- sparse bit-pack of thresholded maps ----
    if (lm && (m >= 0.1f)) {
        atomicOr(&low[r], 1u << c);
        if (m >= 0.2f) atomicOr(&hiw[r], 1u << c);
    }

    // store everything except mag_out now (overlaps with warp-0 hysteresis below)
    out[0 * NPIX + idx] = s0v;
    out[1 * NPIX + idx] = s1v;
    out[2 * NPIX + idx] = s2v;
    out[3 * NPIX + idx] = s3v;
    out[4 * NPIX + idx] = lm ? 1.f : 0.f;
    out[5 * NPIX + idx] = 1.f;
    __syncthreads();

    // ---- hysteresis: 28-bit row masks, 8-connected dilate AND low, in warp 0.
    // Monotone-increasing & bounded -> early exit at fixed point is bit-exact
    // with the reference's fixed 2*H = 56 iterations.
    if (idx < HH) {
        const unsigned MSK = 0x0FFFFFFFu;
        unsigned lo  = low[idx];
        unsigned cur = hiw[idx];
        #pragma unroll 1
        for (int it = 0; it < 2 * HH; ++it) {
            unsigned sp = cur | (cur << 1) | (cur >> 1);
            unsigned up = __shfl_up_sync(MSK, sp, 1);
            unsigned dn = __shfl_down_sync(MSK, sp, 1);
            if (idx == 0)      up = 0u;
            if (idx == HH - 1) dn = 0u;
            unsigned nxt = (sp | up | dn) & lo;
            bool ch = (nxt != cur);
            cur = nxt;
            if (!__any_sync(MSK, ch)) break;
        }
        finalw[idx] = cur;
    }
    __syncthreads();

    out[6 * NPIX + idx] = ((finalw[r] >> c) & 1u) ? 1.f : 0.f;
}

extern "C" void kernel_launch(void* const* d_in, const int* in_sizes, int n_in,
                              void* d_out, int out_size) {
    const float* x    = (const float*)d_in[0];
    const float* mask = (const float*)d_in[1];
    const float* g    = (const float*)d_in[2];
    float* out = (float*)d_out;
    dim3 blk(WW, HH);
    FMNISTCanny_kernel<<<1, blk>>>(x, mask, g, out);
}